// round 5
// baseline (speedup 1.0000x reference)
#include <cuda_runtime.h>
#include <cuda_bf16.h>
#include <cstdint>

// SoftThresholdAttention: B=2, N=4096, C=256, H=4, Dh=64
// d_in: 0=x, 1=q_w, 2=q_b, 3=k_w, 4=k_b, 5=v_w, 6=v_b, 7=o_w, 8=o_b, 9=tau

#define PITCH 65   // qkv/oproj fp32 pitch
#define FP    68   // attn fp32 pitch (16B-aligned rows -> float4 dots)
#define HP    72   // attn bf16 pitch (144B rows: 16B-aligned, conflict-free)

// Scratch (device globals; no allocation allowed)
__device__ float g_Q[8 * 4096 * 64];           // [b*H+h][n][d] fp32
__device__ float g_K[8 * 4096 * 64];
__device__ float g_V[8 * 4096 * 64];
__device__ __nv_bfloat16 g_Qh[8 * 4096 * 64];  // bf16 copies for HMMA filter
__device__ __nv_bfloat16 g_Kh[8 * 4096 * 64];
__device__ float g_A[8192 * 256];              // attention output, [t][c]

// ---- smem layout (bytes) ---------------------------------------------------
#define SM_QH   0u        // 128 x HP bf16  (18432)
#define SM_KH   18432u    // 128 x HP bf16  (18432)
#define SM_QS   36864u    // 128 x FP f32   (34816)
#define SM_KS   71680u
#define SM_VS   106496u
#define SM_OS   141312u
#define SM_BM   176128u   // 128 rows x 4 u32 (2048)
#define SM_DL   178176u   // 128 f32 (512)
#define SM_SVP  178688u   // 4 x 68 f32 (1088)
#define SM_LIST 179776u   // 8 warps x 1024 u32 (32768)
#define SM_TOTAL 212544u

// ---------------------------------------------------------------------------
// QKV projection; also emits bf16 copies of Q and K.
// ---------------------------------------------------------------------------
__global__ __launch_bounds__(256) void qkv_kernel(
    const float* __restrict__ x,
    const float* __restrict__ qw, const float* __restrict__ qb,
    const float* __restrict__ kw, const float* __restrict__ kb,
    const float* __restrict__ vw, const float* __restrict__ vb)
{
    __shared__ float As[64 * PITCH];
    __shared__ float Ws[64 * PITCH];

    const int z = blockIdx.z;
    const float* __restrict__ W    = (z == 0) ? qw : (z == 1) ? kw : vw;
    const float* __restrict__ bias = (z == 0) ? qb : (z == 1) ? kb : vb;
    float* __restrict__ dst        = (z == 0) ? g_Q : (z == 1) ? g_K : g_V;

    const int tr = blockIdx.x * 64;
    const int tc = blockIdx.y * 64;
    const int tid = threadIdx.x;
    const int tx = tid & 15, ty = tid >> 4;

    float acc[4][4] = {};

    for (int kb_ = 0; kb_ < 256; kb_ += 64) {
        for (int idx = tid; idx < 64 * 64; idx += 256) {
            int r = idx >> 6, d = idx & 63;
            As[r * PITCH + d] = x[(tr + r) * 256 + kb_ + d];
            Ws[r * PITCH + d] = W[(tc + r) * 256 + kb_ + d];
        }
        __syncthreads();
        #pragma unroll 8
        for (int d = 0; d < 64; d++) {
            float a[4], b[4];
            #pragma unroll
            for (int i = 0; i < 4; i++) a[i] = As[(ty * 4 + i) * PITCH + d];
            #pragma unroll
            for (int j = 0; j < 4; j++) b[j] = Ws[(tx + 16 * j) * PITCH + d];
            #pragma unroll
            for (int i = 0; i < 4; i++)
                #pragma unroll
                for (int j = 0; j < 4; j++)
                    acc[i][j] += a[i] * b[j];
        }
        __syncthreads();
    }

    #pragma unroll
    for (int i = 0; i < 4; i++) {
        int t = tr + ty * 4 + i;
        int b_ = t >> 12, n = t & 4095;
        #pragma unroll
        for (int j = 0; j < 4; j++) {
            int c = tc + tx + 16 * j;
            int h = c >> 6, dd = c & 63;
            int off = ((b_ * 4 + h) * 4096 + n) * 64 + dd;
            float val = acc[i][j] + bias[c];
            dst[off] = val;
            if (z == 0)      g_Qh[off] = __float2bfloat16(val);
            else if (z == 1) g_Kh[off] = __float2bfloat16(val);
        }
    }
}

// ---------------------------------------------------------------------------
// Attention: bf16 mma.sync (HMMA) filter + exact fp32 sparse recompute.
// grid (32 q-tiles of 128 rows, 8 bh), block 256 (8 warps).
// warp w owns output rows [w*16, w*16+16): computes its own approx scores,
// builds its own candidate bitmap, recomputes exact dots, scatters into Os.
// ---------------------------------------------------------------------------
__global__ __launch_bounds__(256) void attn_kernel(const float* __restrict__ tau_p)
{
    extern __shared__ char smem[];
    const uint32_t* Qh32 = (const uint32_t*)(smem + SM_QH);
    const uint32_t* Kh32 = (const uint32_t*)(smem + SM_KH);
    float*    Qs  = (float*)(smem + SM_QS);
    float*    Ks  = (float*)(smem + SM_KS);
    float*    Vs  = (float*)(smem + SM_VS);
    float*    Os  = (float*)(smem + SM_OS);
    uint32_t* Bm  = (uint32_t*)(smem + SM_BM);
    float*    Dl  = (float*)(smem + SM_DL);
    float*    SVp = (float*)(smem + SM_SVP);
    int*      Ls  = (int*)(smem + SM_LIST);

    const int qt = blockIdx.x, bh = blockIdx.y;
    const int tid  = threadIdx.x;
    const int warp = tid >> 5;
    const int lane = tid & 31;
    const int gid  = lane >> 2;      // mma group id (0..7)
    const int tg   = lane & 3;       // thread in group
    const int r0   = warp * 16;
    const float tau   = tau_p[0];
    const float scale = 0.0625f;                 // 256^-0.5
    const float thrA  = (tau - 0.08f) * 16.0f;   // raw-S filter threshold

    const float* __restrict__ Qg = g_Q + (bh * 4096 + qt * 128) * 64;
    const float* __restrict__ Kg = g_K + bh * 4096 * 64;
    const float* __restrict__ Vg = g_V + bh * 4096 * 64;

    // zero O and Dl
    for (int i = tid; i < 128 * FP; i += 256) Os[i] = 0.0f;
    if (tid < 128) Dl[tid] = 0.0f;

    // load Q: fp32 (pitch FP, float4) + bf16 (pitch HP, uint4)
    {
        const float4* Q4 = (const float4*)Qg;
        #pragma unroll
        for (int it = 0; it < 8; it++) {
            int idx = tid + it * 256;      // < 2048
            int r = idx >> 4, d = (idx & 15) * 4;
            *(float4*)&Qs[r * FP + d] = Q4[idx];
        }
        const uint4* Qh4 = (const uint4*)g_Qh + (bh * 4096 + qt * 128) * 8;
        #pragma unroll
        for (int it = 0; it < 4; it++) {
            int idx = tid + it * 256;      // < 1024
            int row = idx >> 3, cir = idx & 7;   // cir: 8 bf16 per uint4
            *(uint4*)(smem + SM_QH + row * (HP * 2) + cir * 16) = Qh4[idx];
        }
    }
    __syncthreads();

    // A fragments for this warp's 16 rows (Q fixed for whole block):
    // a[ks][0]: m=gid,   k=ks*16+2tg..+1 ; a[ks][1]: m=gid+8
    // a[ks][2]: m=gid,   k+8            ; a[ks][3]: m=gid+8, k+8
    uint32_t afr[4][4];
    {
        const int HPW = HP / 2;   // u32 words per bf16 row
        #pragma unroll
        for (int ks = 0; ks < 4; ks++) {
            int w0 = ks * 8 + tg;
            afr[ks][0] = Qh32[(r0 + gid) * HPW + w0];
            afr[ks][1] = Qh32[(r0 + gid + 8) * HPW + w0];
            afr[ks][2] = Qh32[(r0 + gid) * HPW + w0 + 4];
            afr[ks][3] = Qh32[(r0 + gid + 8) * HPW + w0 + 4];
        }
    }

    // sumV state
    float sv = 0.0f;
    const int svg = tid >> 6, svd = tid & 63;
    const int wbase = warp * 1024;

    for (int kt = 0; kt < 32; kt++) {
        __syncthreads();   // prior tile readers done

        // ---- load K fp32 / V fp32 / K bf16 tiles ---------------------------
        {
            const float4* K4 = (const float4*)(Kg + kt * 128 * 64);
            const float4* V4 = (const float4*)(Vg + kt * 128 * 64);
            #pragma unroll
            for (int it = 0; it < 8; it++) {
                int idx = tid + it * 256;
                int r = idx >> 4, d = (idx & 15) * 4;
                *(float4*)&Ks[r * FP + d] = K4[idx];
                *(float4*)&Vs[r * FP + d] = V4[idx];
            }
            const uint4* Kh4 = (const uint4*)g_Kh + (bh * 4096 + kt * 128) * 8;
            #pragma unroll
            for (int it = 0; it < 4; it++) {
                int idx = tid + it * 256;
                int row = idx >> 3, cir = idx & 7;
                *(uint4*)(smem + SM_KH + row * (HP * 2) + cir * 16) = Kh4[idx];
            }
        }
        __syncthreads();

        // ---- sumV partial ---------------------------------------------------
        #pragma unroll 8
        for (int k = 0; k < 32; k++)
            sv += Vs[(svg * 32 + k) * FP + svd];

        // ---- approx scores via mma.sync; build bitmap warp-locally ---------
        {
            const int HPW = HP / 2;
            uint32_t wacc = 0;
            #pragma unroll
            for (int nb = 0; nb < 16; nb++) {
                float d0 = 0.0f, d1 = 0.0f, d2 = 0.0f, d3 = 0.0f;
                #pragma unroll
                for (int ks = 0; ks < 4; ks++) {
                    // B frag: n = nb*8+gid (key), k = ks*16+2tg (+8 for b1)
                    uint32_t b0 = Kh32[(nb * 8 + gid) * HPW + ks * 8 + tg];
                    uint32_t b1 = Kh32[(nb * 8 + gid) * HPW + ks * 8 + tg + 4];
                    asm volatile(
                        "mma.sync.aligned.m16n8k16.row.col.f32.bf16.bf16.f32 "
                        "{%0,%1,%2,%3}, {%4,%5,%6,%7}, {%8,%9}, {%0,%1,%2,%3};"
                        : "+f"(d0), "+f"(d1), "+f"(d2), "+f"(d3)
                        : "r"(afr[ks][0]), "r"(afr[ks][1]),
                          "r"(afr[ks][2]), "r"(afr[ks][3]),
                          "r"(b0), "r"(b1));
                }
                // d0: (m=gid, n=2tg) d1: (gid, 2tg+1) d2: (gid+8, 2tg) d3: (gid+8, 2tg+1)
                unsigned B0 = __ballot_sync(0xffffffffu, d0 > thrA);
                unsigned B1 = __ballot_sync(0xffffffffu, d1 > thrA);
                unsigned B2 = __ballot_sync(0xffffffffu, d2 > thrA);
                unsigned B3 = __ballot_sync(0xffffffffu, d3 > thrA);
                if (lane < 16) {
                    int row = lane;   // row within warp tile
                    unsigned ne, no;
                    if (row < 8) { ne = (B0 >> (row * 4)) & 0xF; no = (B1 >> (row * 4)) & 0xF; }
                    else         { ne = (B2 >> ((row - 8) * 4)) & 0xF; no = (B3 >> ((row - 8) * 4)) & 0xF; }
                    unsigned byte =  (ne & 1u)        | ((no & 1u) << 1)
                                  | ((ne & 2u) << 1)  | ((no & 2u) << 2)
                                  | ((ne & 4u) << 2)  | ((no & 4u) << 3)
                                  | ((ne & 8u) << 3)  | ((no & 8u) << 4);
                    wacc |= byte << ((nb & 3) * 8);
                    if ((nb & 3) == 3) {
                        Bm[(r0 + row) * 4 + (nb >> 2)] = wacc;
                        wacc = 0;
                    }
                }
            }
        }
        __syncwarp();

        // ---- candidate pass: exact fp32 recompute + scatter ----------------
        #pragma unroll
        for (int g = 0; g < 2; g++) {
            int row = r0 + g * 8 + (lane >> 2);
            int word = lane & 3;
            uint32_t m = Bm[row * 4 + word];
            int cnt = __popc(m);
            int pre = cnt;
            #pragma unroll
            for (int off = 1; off < 32; off <<= 1) {
                int n = __shfl_up_sync(0xffffffffu, pre, off);
                if (lane >= off) pre += n;
            }
            int base = pre - cnt;
            int total = __shfl_sync(0xffffffffu, pre, 31);
            int i = 0;
            while (m) {
                int c = __ffs(m) - 1;
                m &= m - 1;
                Ls[wbase + base + i] = (row << 16) | (word * 32 + c);
                i++;
            }
            __syncwarp();

            for (int cb = 0; cb < total; cb += 32) {
                int ci = cb + lane;
                int e = (ci < total) ? Ls[wbase + ci] : -1;
                float w = 0.0f;
                if (e >= 0) {
                    int r = e >> 16, c = e & 0xFFFF;
                    const float4* qr = (const float4*)&Qs[r * FP];
                    const float4* kc = (const float4*)&Ks[c * FP];
                    float a0 = 0.0f, a1 = 0.0f, a2 = 0.0f, a3 = 0.0f;
                    #pragma unroll
                    for (int d = 0; d < 16; d++) {
                        float4 qv = qr[d], kv = kc[d];
                        a0 += qv.x * kv.x;
                        a1 += qv.y * kv.y;
                        a2 += qv.z * kv.z;
                        a3 += qv.w * kv.w;
                    }
                    float v = ((a0 + a1) + (a2 + a3)) * scale;
                    if (v > tau) w = __expf(v) - 1.0f;
                }
                unsigned vm = __ballot_sync(0xffffffffu, w > 0.0f);
                while (vm) {
                    int j = __ffs(vm) - 1;
                    vm &= vm - 1;
                    float wj = __shfl_sync(0xffffffffu, w, j);
                    int   ej = __shfl_sync(0xffffffffu, e, j);
                    int r = ej >> 16, c = ej & 0xFFFF;
                    Os[r * FP + lane]      += wj * Vs[c * FP + lane];
                    Os[r * FP + lane + 32] += wj * Vs[c * FP + lane + 32];
                    if (lane == 0) Dl[r] += wj;
                }
            }
            __syncwarp();
        }
    }

    // ---- combine sumV partials --------------------------------------------
    __syncthreads();
    SVp[svg * 68 + svd] = sv;
    __syncthreads();
    float sv0 = SVp[lane]      + SVp[68 + lane]      + SVp[136 + lane]      + SVp[204 + lane];
    float sv1 = SVp[lane + 32] + SVp[68 + lane + 32] + SVp[136 + lane + 32] + SVp[204 + lane + 32];

    // ---- finalize: rows owned by this warp --------------------------------
    const int b_ = bh >> 2, h = bh & 3;
    const int tbase = b_ * 4096 + qt * 128;
    #pragma unroll
    for (int rr = 0; rr < 16; rr++) {
        int r = r0 + rr;
        float inv = 1.0f / (4096.0f + Dl[r]);
        int t = tbase + r;
        g_A[t * 256 + h * 64 + lane]      = (sv0 + Os[r * FP + lane]) * inv;
        g_A[t * 256 + h * 64 + lane + 32] = (sv1 + Os[r * FP + lane + 32]) * inv;
    }
}

// ---------------------------------------------------------------------------
// Output projection: out[t,c] = sum_d g_A[t,d] * o_w[c,d] + o_b[c]
// ---------------------------------------------------------------------------
__global__ __launch_bounds__(256) void oproj_kernel(
    const float* __restrict__ ow, const float* __restrict__ ob,
    float* __restrict__ out)
{
    __shared__ float As[64 * PITCH];
    __shared__ float Ws[64 * PITCH];

    const int tr = blockIdx.x * 64;
    const int tc = blockIdx.y * 64;
    const int tid = threadIdx.x;
    const int tx = tid & 15, ty = tid >> 4;

    float acc[4][4] = {};

    for (int kb_ = 0; kb_ < 256; kb_ += 64) {
        for (int idx = tid; idx < 64 * 64; idx += 256) {
            int r = idx >> 6, d = idx & 63;
            As[r * PITCH + d] = g_A[(tr + r) * 256 + kb_ + d];
            Ws[r * PITCH + d] = ow[(tc + r) * 256 + kb_ + d];
        }
        __syncthreads();
        #pragma unroll 8
        for (int d = 0; d < 64; d++) {
            float a[4], b[4];
            #pragma unroll
            for (int i = 0; i < 4; i++) a[i] = As[(ty * 4 + i) * PITCH + d];
            #pragma unroll
            for (int j = 0; j < 4; j++) b[j] = Ws[(tx + 16 * j) * PITCH + d];
            #pragma unroll
            for (int i = 0; i < 4; i++)
                #pragma unroll
                for (int j = 0; j < 4; j++)
                    acc[i][j] += a[i] * b[j];
        }
        __syncthreads();
    }

    #pragma unroll
    for (int i = 0; i < 4; i++) {
        int t = tr + ty * 4 + i;
        #pragma unroll
        for (int j = 0; j < 4; j++) {
            int c = tc + tx + 16 * j;
            out[t * 256 + c] = acc[i][j] + ob[c];
        }
    }
}

// ---------------------------------------------------------------------------
extern "C" void kernel_launch(void* const* d_in, const int* in_sizes, int n_in,
                              void* d_out, int out_size)
{
    const float* x   = (const float*)d_in[0];
    const float* qw  = (const float*)d_in[1];
    const float* qb  = (const float*)d_in[2];
    const float* kw  = (const float*)d_in[3];
    const float* kb  = (const float*)d_in[4];
    const float* vw  = (const float*)d_in[5];
    const float* vb  = (const float*)d_in[6];
    const float* ow  = (const float*)d_in[7];
    const float* ob  = (const float*)d_in[8];
    const float* tau = (const float*)d_in[9];
    float* out = (float*)d_out;

    // QKV projections (+ bf16 Q/K copies)
    dim3 gq(128, 4, 3);
    qkv_kernel<<<gq, 256>>>(x, qw, qb, kw, kb, vw, vb);

    // attention: HMMA filter + exact sparse recompute
    static bool attr_set = false;
    if (!attr_set) {
        cudaFuncSetAttribute(attn_kernel,
                             cudaFuncAttributeMaxDynamicSharedMemorySize,
                             SM_TOTAL);
        attr_set = true;
    }
    dim3 ga(32, 8);
    attn_kernel<<<ga, 256, SM_TOTAL>>>(tau);

    // output projection
    dim3 go(128, 4);
    oproj_kernel<<<go, 256>>>(ow, ob, out);
}

// round 6
// speedup vs baseline: 1.4942x; 1.4942x over previous
#include <cuda_runtime.h>
#include <cuda_bf16.h>
#include <cstdint>

// SoftThresholdAttention: B=2, N=4096, C=256, H=4, Dh=64
// d_in: 0=x, 1=q_w, 2=q_b, 3=k_w, 4=k_b, 5=v_w, 6=v_b, 7=o_w, 8=o_b, 9=tau

#define PITCH 65   // qkv/oproj fp32 pitch
#define FP    68   // attn fp32 pitch (16B-aligned rows)

// Scratch (device globals; no allocation allowed)
__device__ float g_Q[8 * 4096 * 64];   // [b*H+h][n][d]
__device__ float g_K[8 * 4096 * 64];
__device__ float g_V[8 * 4096 * 64];
__device__ float g_A[8192 * 256];      // attention output, [t][c]

// ---- attn smem layout (bytes) ----------------------------------------------
#define SM_QS   0u         // 256 x FP f32 (69632)
#define SM_KS   69632u     // 128 x FP f32 (34816)
#define SM_VS   104448u    // 128 x FP f32 (34816)
#define SM_BM   139264u    // 256 rows x 4 u32 (4096)
#define SM_LS   143360u    // 16 warps x 512 int (32768)
#define SM_WL   176128u    // 16 warps x 512 f32 (32768)
#define SM_SVP  208896u    // 8 x 68 f32 (2176)
#define SM_TOTAL 211072u

// pack two fp32 -> bf16x2 register (lo = first element, as mma expects)
__device__ __forceinline__ uint32_t bf2(float lo, float hi) {
    uint32_t r;
    asm("cvt.rn.bf16x2.f32 %0, %1, %2;" : "=r"(r) : "f"(hi), "f"(lo));
    return r;
}

// ---------------------------------------------------------------------------
// QKV projection: out[t,c] = sum_d x[t,d] * W[c,d] + b[c]; store [bh][n][d]
// ---------------------------------------------------------------------------
__global__ __launch_bounds__(256) void qkv_kernel(
    const float* __restrict__ x,
    const float* __restrict__ qw, const float* __restrict__ qb,
    const float* __restrict__ kw, const float* __restrict__ kb,
    const float* __restrict__ vw, const float* __restrict__ vb)
{
    __shared__ float As[64 * PITCH];
    __shared__ float Ws[64 * PITCH];

    const int z = blockIdx.z;
    const float* __restrict__ W    = (z == 0) ? qw : (z == 1) ? kw : vw;
    const float* __restrict__ bias = (z == 0) ? qb : (z == 1) ? kb : vb;
    float* __restrict__ dst        = (z == 0) ? g_Q : (z == 1) ? g_K : g_V;

    const int tr = blockIdx.x * 64;
    const int tc = blockIdx.y * 64;
    const int tid = threadIdx.x;
    const int tx = tid & 15, ty = tid >> 4;

    float acc[4][4] = {};

    for (int kb_ = 0; kb_ < 256; kb_ += 64) {
        for (int idx = tid; idx < 64 * 64; idx += 256) {
            int r = idx >> 6, d = idx & 63;
            As[r * PITCH + d] = x[(tr + r) * 256 + kb_ + d];
            Ws[r * PITCH + d] = W[(tc + r) * 256 + kb_ + d];
        }
        __syncthreads();
        #pragma unroll 8
        for (int d = 0; d < 64; d++) {
            float a[4], b[4];
            #pragma unroll
            for (int i = 0; i < 4; i++) a[i] = As[(ty * 4 + i) * PITCH + d];
            #pragma unroll
            for (int j = 0; j < 4; j++) b[j] = Ws[(tx + 16 * j) * PITCH + d];
            #pragma unroll
            for (int i = 0; i < 4; i++)
                #pragma unroll
                for (int j = 0; j < 4; j++)
                    acc[i][j] += a[i] * b[j];
        }
        __syncthreads();
    }

    #pragma unroll
    for (int i = 0; i < 4; i++) {
        int t = tr + ty * 4 + i;
        int b_ = t >> 12, n = t & 4095;
        #pragma unroll
        for (int j = 0; j < 4; j++) {
            int c = tc + tx + 16 * j;
            int h = c >> 6, dd = c & 63;
            dst[((b_ * 4 + h) * 4096 + n) * 64 + dd] = acc[i][j] + bias[c];
        }
    }
}

// ---------------------------------------------------------------------------
// Attention: bf16 mma.sync filter (fragments cvt'd from fp32 smem) + exact
// fp32 recompute of candidates. grid (16 q-tiles of 256 rows, 8 bh),
// block 512 = 16 warps; warp owns 16 rows, O in registers.
// denom = 4096 + sum(e^v - 1 over v>tau); O = (sumV + sum w*V) / denom.
// ---------------------------------------------------------------------------
__global__ __launch_bounds__(512, 1) void attn_kernel(const float* __restrict__ tau_p)
{
    extern __shared__ char smem[];
    float*    Qs  = (float*)(smem + SM_QS);
    float*    Ks  = (float*)(smem + SM_KS);
    float*    Vs  = (float*)(smem + SM_VS);
    uint32_t* Bm  = (uint32_t*)(smem + SM_BM);
    int*      Ls  = (int*)(smem + SM_LS);
    float*    Wl  = (float*)(smem + SM_WL);
    float*    SVp = (float*)(smem + SM_SVP);

    const int qt = blockIdx.x, bh = blockIdx.y;
    const int tid  = threadIdx.x;
    const int warp = tid >> 5;
    const int lane = tid & 31;
    const int gid  = lane >> 2;      // mma group id (0..7)
    const int tg   = lane & 3;       // thread in group
    const int R0   = warp * 16;      // warp-owned rows [R0, R0+16)
    const float tau   = tau_p[0];
    const float scale = 0.0625f;                // 256^-0.5
    const float thrA  = (tau - 0.1f) * 16.0f;   // raw-S filter threshold

    const float* __restrict__ Qg = g_Q + (bh * 4096 + qt * 256) * 64;
    const float* __restrict__ Kg = g_K + bh * 4096 * 64;
    const float* __restrict__ Vg = g_V + bh * 4096 * 64;

    // load Q tile (256 x 64) fp32
    {
        const float4* Q4 = (const float4*)Qg;
        #pragma unroll
        for (int it = 0; it < 8; it++) {
            int idx = tid + it * 512;      // < 4096
            int r = idx >> 4, d = (idx & 15) * 4;
            *(float4*)&Qs[r * FP + d] = Q4[idx];
        }
    }
    __syncthreads();

    // A fragments (warp's 16 rows), converted fp32->bf16 from Qs. Layout per
    // PTX m16n8k16 row-major A:
    //   afr[ks][0]: (gid,   k=ks*16+2tg..+1)   afr[ks][1]: (gid+8, same)
    //   afr[ks][2]: (gid,   k+8)               afr[ks][3]: (gid+8, k+8)
    uint32_t afr[4][4];
    #pragma unroll
    for (int ks = 0; ks < 4; ks++) {
        int c0 = ks * 16 + 2 * tg;
        float2 q00 = *(const float2*)&Qs[(R0 + gid) * FP + c0];
        float2 q10 = *(const float2*)&Qs[(R0 + gid + 8) * FP + c0];
        float2 q01 = *(const float2*)&Qs[(R0 + gid) * FP + c0 + 8];
        float2 q11 = *(const float2*)&Qs[(R0 + gid + 8) * FP + c0 + 8];
        afr[ks][0] = bf2(q00.x, q00.y);
        afr[ks][1] = bf2(q10.x, q10.y);
        afr[ks][2] = bf2(q01.x, q01.y);
        afr[ks][3] = bf2(q11.x, q11.y);
    }

    float O[16][2] = {};
    float dl[16]   = {};
    float sv = 0.0f;
    const int svg = tid >> 6, svd = tid & 63;   // 8 groups x 16 keys
    const int wb = warp * 512;

    for (int kt = 0; kt < 32; kt++) {
        __syncthreads();   // prior tile readers done

        // ---- load K/V tiles (128 x 64) fp32 --------------------------------
        {
            const float4* K4 = (const float4*)(Kg + kt * 128 * 64);
            const float4* V4 = (const float4*)(Vg + kt * 128 * 64);
            #pragma unroll
            for (int it = 0; it < 4; it++) {
                int idx = tid + it * 512;      // < 2048
                int r = idx >> 4, d = (idx & 15) * 4;
                *(float4*)&Ks[r * FP + d] = K4[idx];
                *(float4*)&Vs[r * FP + d] = V4[idx];
            }
        }
        __syncthreads();

        // ---- sumV partial ---------------------------------------------------
        #pragma unroll 8
        for (int k = 0; k < 16; k++)
            sv += Vs[(svg * 16 + k) * FP + svd];

        // ---- approx scores via mma.sync; bitmap for warp's 16 rows ---------
        {
            uint32_t wacc = 0;
            #pragma unroll
            for (int nb = 0; nb < 16; nb++) {
                float d0 = 0.0f, d1 = 0.0f, d2 = 0.0f, d3 = 0.0f;
                #pragma unroll
                for (int ks = 0; ks < 4; ks++) {
                    int kr = nb * 8 + gid;            // key (B col n)
                    int c0 = ks * 16 + 2 * tg;        // k index
                    float2 k0 = *(const float2*)&Ks[kr * FP + c0];
                    float2 k1 = *(const float2*)&Ks[kr * FP + c0 + 8];
                    uint32_t b0 = bf2(k0.x, k0.y);
                    uint32_t b1 = bf2(k1.x, k1.y);
                    asm volatile(
                        "mma.sync.aligned.m16n8k16.row.col.f32.bf16.bf16.f32 "
                        "{%0,%1,%2,%3}, {%4,%5,%6,%7}, {%8,%9}, {%0,%1,%2,%3};"
                        : "+f"(d0), "+f"(d1), "+f"(d2), "+f"(d3)
                        : "r"(afr[ks][0]), "r"(afr[ks][1]),
                          "r"(afr[ks][2]), "r"(afr[ks][3]),
                          "r"(b0), "r"(b1));
                }
                // d0:(gid,2tg) d1:(gid,2tg+1) d2:(gid+8,2tg) d3:(gid+8,2tg+1)
                unsigned B0 = __ballot_sync(0xffffffffu, d0 > thrA);
                unsigned B1 = __ballot_sync(0xffffffffu, d1 > thrA);
                unsigned B2 = __ballot_sync(0xffffffffu, d2 > thrA);
                unsigned B3 = __ballot_sync(0xffffffffu, d3 > thrA);
                if (lane < 16) {
                    int row = lane;
                    unsigned ne, no;
                    if (row < 8) { ne = (B0 >> (row * 4)) & 0xF; no = (B1 >> (row * 4)) & 0xF; }
                    else         { ne = (B2 >> ((row - 8) * 4)) & 0xF; no = (B3 >> ((row - 8) * 4)) & 0xF; }
                    unsigned byte =  (ne & 1u)        | ((no & 1u) << 1)
                                  | ((ne & 2u) << 1)  | ((no & 2u) << 2)
                                  | ((ne & 4u) << 2)  | ((no & 4u) << 3)
                                  | ((ne & 8u) << 3)  | ((no & 8u) << 4);
                    wacc |= byte << ((nb & 3) * 8);
                    if ((nb & 3) == 3) {
                        Bm[(R0 + row) * 4 + (nb >> 2)] = wacc;
                        wacc = 0;
                    }
                }
            }
        }
        __syncwarp();

        // ---- candidate passes: 4 groups of 4 rows --------------------------
        #pragma unroll
        for (int g = 0; g < 4; g++) {
            // lane < 16 owns (rowL = g*4 + lane>>2, word = lane&3)
            uint32_t m = 0;
            int cnt = 0;
            int rowL = g * 4 + (lane >> 2);
            if (lane < 16) {
                m = Bm[(R0 + rowL) * 4 + (lane & 3)];
                cnt = __popc(m);
            }
            int pre = cnt;
            #pragma unroll
            for (int off = 1; off < 16; off <<= 1) {
                int n = __shfl_up_sync(0xffffffffu, pre, off);
                if (lane >= off && lane < 16) pre += n;
            }
            int base = pre - cnt;
            int total = __shfl_sync(0xffffffffu, pre, 15);
            {
                int i = 0;
                while (m) {
                    int c = __ffs(m) - 1;
                    m &= m - 1;
                    Ls[wb + base + i] = (rowL << 16) | ((lane & 3) * 32 + c);
                    i++;
                }
            }
            __syncwarp();

            // exact fp32 recompute, batched one candidate per lane
            for (int cb = 0; cb < total; cb += 32) {
                int ci = cb + lane;
                float w = 0.0f;
                if (ci < total) {
                    int e = Ls[wb + ci];
                    int rl = e >> 16, c = e & 0xFFFF;
                    const float4* qr = (const float4*)&Qs[(R0 + rl) * FP];
                    const float4* kc = (const float4*)&Ks[c * FP];
                    float a0 = 0.0f, a1 = 0.0f, a2 = 0.0f, a3 = 0.0f;
                    #pragma unroll
                    for (int d = 0; d < 16; d++) {
                        float4 qv = qr[d], kv = kc[d];
                        a0 += qv.x * kv.x;
                        a1 += qv.y * kv.y;
                        a2 += qv.z * kv.z;
                        a3 += qv.w * kv.w;
                    }
                    float v = ((a0 + a1) + (a2 + a3)) * scale;
                    if (v > tau) w = __expf(v) - 1.0f;
                }
                if (ci < total) Wl[wb + ci] = w;
            }
            __syncwarp();

            // scatter: list is row-grouped, so O index is compile-time
            #pragma unroll
            for (int j = 0; j < 4; j++) {
                int startj = (j == 0) ? 0 : __shfl_sync(0xffffffffu, pre, j * 4 - 1);
                int endj   = __shfl_sync(0xffffffffu, pre, j * 4 + 3);
                for (int t = startj; t < endj; t++) {
                    float w = Wl[wb + t];               // broadcast
                    int   c = Ls[wb + t] & 0xFFFF;      // broadcast
                    O[g * 4 + j][0] += w * Vs[c * FP + lane];
                    O[g * 4 + j][1] += w * Vs[c * FP + lane + 32];
                    dl[g * 4 + j] += w;
                }
            }
            __syncwarp();
        }
    }

    // ---- combine sumV partials --------------------------------------------
    __syncthreads();
    SVp[svg * 68 + svd] = sv;
    __syncthreads();
    float sv0 = 0.0f, sv1 = 0.0f;
    #pragma unroll
    for (int gg = 0; gg < 8; gg++) {
        sv0 += SVp[gg * 68 + lane];
        sv1 += SVp[gg * 68 + lane + 32];
    }

    // ---- finalize: rows owned by this warp --------------------------------
    const int b_ = bh >> 2, h = bh & 3;
    const int tbase = b_ * 4096 + qt * 256;
    #pragma unroll
    for (int i = 0; i < 16; i++) {
        float inv = 1.0f / (4096.0f + dl[i]);
        int t = tbase + R0 + i;
        g_A[t * 256 + h * 64 + lane]      = (sv0 + O[i][0]) * inv;
        g_A[t * 256 + h * 64 + lane + 32] = (sv1 + O[i][1]) * inv;
    }
}

// ---------------------------------------------------------------------------
// Output projection: out[t,c] = sum_d g_A[t,d] * o_w[c,d] + o_b[c]
// ---------------------------------------------------------------------------
__global__ __launch_bounds__(256) void oproj_kernel(
    const float* __restrict__ ow, const float* __restrict__ ob,
    float* __restrict__ out)
{
    __shared__ float As[64 * PITCH];
    __shared__ float Ws[64 * PITCH];

    const int tr = blockIdx.x * 64;
    const int tc = blockIdx.y * 64;
    const int tid = threadIdx.x;
    const int tx = tid & 15, ty = tid >> 4;

    float acc[4][4] = {};

    for (int kb_ = 0; kb_ < 256; kb_ += 64) {
        for (int idx = tid; idx < 64 * 64; idx += 256) {
            int r = idx >> 6, d = idx & 63;
            As[r * PITCH + d] = g_A[(tr + r) * 256 + kb_ + d];
            Ws[r * PITCH + d] = ow[(tc + r) * 256 + kb_ + d];
        }
        __syncthreads();
        #pragma unroll 8
        for (int d = 0; d < 64; d++) {
            float a[4], b[4];
            #pragma unroll
            for (int i = 0; i < 4; i++) a[i] = As[(ty * 4 + i) * PITCH + d];
            #pragma unroll
            for (int j = 0; j < 4; j++) b[j] = Ws[(tx + 16 * j) * PITCH + d];
            #pragma unroll
            for (int i = 0; i < 4; i++)
                #pragma unroll
                for (int j = 0; j < 4; j++)
                    acc[i][j] += a[i] * b[j];
        }
        __syncthreads();
    }

    #pragma unroll
    for (int i = 0; i < 4; i++) {
        int t = tr + ty * 4 + i;
        #pragma unroll
        for (int j = 0; j < 4; j++) {
            int c = tc + tx + 16 * j;
            out[t * 256 + c] = acc[i][j] + ob[c];
        }
    }
}

// ---------------------------------------------------------------------------
extern "C" void kernel_launch(void* const* d_in, const int* in_sizes, int n_in,
                              void* d_out, int out_size)
{
    const float* x   = (const float*)d_in[0];
    const float* qw  = (const float*)d_in[1];
    const float* qb  = (const float*)d_in[2];
    const float* kw  = (const float*)d_in[3];
    const float* kb  = (const float*)d_in[4];
    const float* vw  = (const float*)d_in[5];
    const float* vb  = (const float*)d_in[6];
    const float* ow  = (const float*)d_in[7];
    const float* ob  = (const float*)d_in[8];
    const float* tau = (const float*)d_in[9];
    float* out = (float*)d_out;

    // QKV projections
    dim3 gq(128, 4, 3);
    qkv_kernel<<<gq, 256>>>(x, qw, qb, kw, kb, vw, vb);

    // attention: HMMA filter + exact sparse recompute
    static bool attr_set = false;
    if (!attr_set) {
        cudaFuncSetAttribute(attn_kernel,
                             cudaFuncAttributeMaxDynamicSharedMemorySize,
                             SM_TOTAL);
        attr_set = true;
    }
    dim3 ga(16, 8);
    attn_kernel<<<ga, 512, SM_TOTAL>>>(tau);

    // output projection
    dim3 go(128, 4);
    oproj_kernel<<<go, 256>>>(ow, ob, out);
}

// round 7
// speedup vs baseline: 1.7569x; 1.1758x over previous
#include <cuda_runtime.h>
#include <cuda_bf16.h>
#include <cstdint>

// SoftThresholdAttention: B=2, N=4096, C=256, H=4, Dh=64
// d_in: 0=x, 1=q_w, 2=q_b, 3=k_w, 4=k_b, 5=v_w, 6=v_b, 7=o_w, 8=o_b, 9=tau

#define PITCH 65   // qkv/oproj fp32 pitch
#define FP    68   // attn fp32 pitch (16B-aligned rows)
#define HPW   36   // bf16 K tile pitch in u32 words (72 halves = 144B rows)

// Scratch (device globals; no allocation allowed)
__device__ float g_Q[8 * 4096 * 64];   // [b*H+h][n][d]
__device__ float g_K[8 * 4096 * 64];
__device__ float g_V[8 * 4096 * 64];
__device__ float g_A[8192 * 256];      // attention output, [t][c]

// ---- attn smem layout (bytes) ----------------------------------------------
#define SM_QS   0u         // 256 x FP f32   (69632)
#define SM_KS   69632u     // 128 x FP f32   (34816)
#define SM_VS   104448u    // 128 x FP f32   (34816)
#define SM_KH   139264u    // 128 x HPW u32  (18432)  bf16 K tile
#define SM_BM   157696u    // 256 rows x 4 u32 (4096)
#define SM_LS   161792u    // 16 warps x 384 int (24576)
#define SM_WL   186368u    // 16 warps x 384 f32 (24576)
#define SM_SVP  210944u    // 8 x 68 f32 (2176)
#define SM_TOTAL 213120u

// pack two fp32 -> bf16x2 register (lo = first element, as mma expects)
__device__ __forceinline__ uint32_t bf2(float lo, float hi) {
    uint32_t r;
    asm("cvt.rn.bf16x2.f32 %0, %1, %2;" : "=r"(r) : "f"(hi), "f"(lo));
    return r;
}

// ---------------------------------------------------------------------------
// QKV projection: out[t,c] = sum_d x[t,d] * W[c,d] + b[c]; store [bh][n][d]
// ---------------------------------------------------------------------------
__global__ __launch_bounds__(256) void qkv_kernel(
    const float* __restrict__ x,
    const float* __restrict__ qw, const float* __restrict__ qb,
    const float* __restrict__ kw, const float* __restrict__ kb,
    const float* __restrict__ vw, const float* __restrict__ vb)
{
    __shared__ float As[64 * PITCH];
    __shared__ float Ws[64 * PITCH];

    const int z = blockIdx.z;
    const float* __restrict__ W    = (z == 0) ? qw : (z == 1) ? kw : vw;
    const float* __restrict__ bias = (z == 0) ? qb : (z == 1) ? kb : vb;
    float* __restrict__ dst        = (z == 0) ? g_Q : (z == 1) ? g_K : g_V;

    const int tr = blockIdx.x * 64;
    const int tc = blockIdx.y * 64;
    const int tid = threadIdx.x;
    const int tx = tid & 15, ty = tid >> 4;

    float acc[4][4] = {};

    for (int kb_ = 0; kb_ < 256; kb_ += 64) {
        for (int idx = tid; idx < 64 * 64; idx += 256) {
            int r = idx >> 6, d = idx & 63;
            As[r * PITCH + d] = x[(tr + r) * 256 + kb_ + d];
            Ws[r * PITCH + d] = W[(tc + r) * 256 + kb_ + d];
        }
        __syncthreads();
        #pragma unroll 8
        for (int d = 0; d < 64; d++) {
            float a[4], b[4];
            #pragma unroll
            for (int i = 0; i < 4; i++) a[i] = As[(ty * 4 + i) * PITCH + d];
            #pragma unroll
            for (int j = 0; j < 4; j++) b[j] = Ws[(tx + 16 * j) * PITCH + d];
            #pragma unroll
            for (int i = 0; i < 4; i++)
                #pragma unroll
                for (int j = 0; j < 4; j++)
                    acc[i][j] += a[i] * b[j];
        }
        __syncthreads();
    }

    #pragma unroll
    for (int i = 0; i < 4; i++) {
        int t = tr + ty * 4 + i;
        int b_ = t >> 12, n = t & 4095;
        #pragma unroll
        for (int j = 0; j < 4; j++) {
            int c = tc + tx + 16 * j;
            int h = c >> 6, dd = c & 63;
            dst[((b_ * 4 + h) * 4096 + n) * 64 + dd] = acc[i][j] + bias[c];
        }
    }
}

// ---------------------------------------------------------------------------
// Attention: bf16 mma.sync filter + exact fp32 recompute of candidates.
// grid (16 q-tiles of 256 rows, 8 bh), block 512 = 16 warps; warp owns 16
// rows, O in registers. Exact dot uses single sequential accumulator over d
// (matches reference gate decisions on borderline scores).
// denom = 4096 + sum(e^v - 1 over v>tau); O = (sumV + sum w*V) / denom.
// ---------------------------------------------------------------------------
__global__ __launch_bounds__(512, 1) void attn_kernel(const float* __restrict__ tau_p)
{
    extern __shared__ char smem[];
    float*    Qs   = (float*)(smem + SM_QS);
    float*    Ks   = (float*)(smem + SM_KS);
    float*    Vs   = (float*)(smem + SM_VS);
    uint32_t* Kh32 = (uint32_t*)(smem + SM_KH);
    uint32_t* Bm   = (uint32_t*)(smem + SM_BM);
    int*      Ls   = (int*)(smem + SM_LS);
    float*    Wl   = (float*)(smem + SM_WL);
    float*    SVp  = (float*)(smem + SM_SVP);

    const int qt = blockIdx.x, bh = blockIdx.y;
    const int tid  = threadIdx.x;
    const int warp = tid >> 5;
    const int lane = tid & 31;
    const int gid  = lane >> 2;      // mma group id (0..7)
    const int tg   = lane & 3;       // thread in group
    const int R0   = warp * 16;      // warp-owned rows [R0, R0+16)
    const float tau   = tau_p[0];
    const float scale = 0.0625f;                 // 256^-0.5
    const float thrA  = (tau - 0.03f) * 16.0f;   // raw-S filter threshold

    const float* __restrict__ Qg = g_Q + (bh * 4096 + qt * 256) * 64;
    const float* __restrict__ Kg = g_K + bh * 4096 * 64;
    const float* __restrict__ Vg = g_V + bh * 4096 * 64;

    // load Q tile (256 x 64) fp32
    {
        const float4* Q4 = (const float4*)Qg;
        #pragma unroll
        for (int it = 0; it < 8; it++) {
            int idx = tid + it * 512;      // < 4096
            int r = idx >> 4, d = (idx & 15) * 4;
            *(float4*)&Qs[r * FP + d] = Q4[idx];
        }
    }
    __syncthreads();

    // A fragments (warp's 16 rows) converted fp32->bf16 from Qs.
    // afr[ks][0]:(gid, k=ks*16+2tg) [1]:(gid+8) [2]:(gid, k+8) [3]:(gid+8, k+8)
    uint32_t afr[4][4];
    #pragma unroll
    for (int ks = 0; ks < 4; ks++) {
        int c0 = ks * 16 + 2 * tg;
        float2 q00 = *(const float2*)&Qs[(R0 + gid) * FP + c0];
        float2 q10 = *(const float2*)&Qs[(R0 + gid + 8) * FP + c0];
        float2 q01 = *(const float2*)&Qs[(R0 + gid) * FP + c0 + 8];
        float2 q11 = *(const float2*)&Qs[(R0 + gid + 8) * FP + c0 + 8];
        afr[ks][0] = bf2(q00.x, q00.y);
        afr[ks][1] = bf2(q10.x, q10.y);
        afr[ks][2] = bf2(q01.x, q01.y);
        afr[ks][3] = bf2(q11.x, q11.y);
    }

    float O[16][2] = {};
    float dl[16]   = {};
    float sv = 0.0f;
    const int svg = tid >> 6, svd = tid & 63;   // 8 groups x 16 keys
    const int wb = warp * 384;

    for (int kt = 0; kt < 32; kt++) {
        __syncthreads();   // prior tile readers done

        // ---- load K/V tiles (128 x 64) fp32 + build bf16 K tile ------------
        {
            const float4* K4 = (const float4*)(Kg + kt * 128 * 64);
            const float4* V4 = (const float4*)(Vg + kt * 128 * 64);
            #pragma unroll
            for (int it = 0; it < 4; it++) {
                int idx = tid + it * 512;      // < 2048
                int r = idx >> 4, d = (idx & 15) * 4;
                float4 kv = K4[idx];
                *(float4*)&Ks[r * FP + d] = kv;
                *(float4*)&Vs[r * FP + d] = V4[idx];
                uint32_t w0 = bf2(kv.x, kv.y);
                uint32_t w1 = bf2(kv.z, kv.w);
                *(uint2*)&Kh32[r * HPW + (d >> 1)] = make_uint2(w0, w1);
            }
        }
        __syncthreads();

        // ---- sumV partial ---------------------------------------------------
        #pragma unroll 8
        for (int k = 0; k < 16; k++)
            sv += Vs[(svg * 16 + k) * FP + svd];

        // ---- approx scores via mma.sync; bitmap for warp's 16 rows ---------
        {
            uint32_t wacc = 0;
            #pragma unroll
            for (int nb = 0; nb < 16; nb++) {
                float d0 = 0.0f, d1 = 0.0f, d2 = 0.0f, d3 = 0.0f;
                #pragma unroll
                for (int ks = 0; ks < 4; ks++) {
                    int kr = nb * 8 + gid;            // key (B col n)
                    uint32_t b0 = Kh32[kr * HPW + ks * 8 + tg];
                    uint32_t b1 = Kh32[kr * HPW + ks * 8 + tg + 4];
                    asm volatile(
                        "mma.sync.aligned.m16n8k16.row.col.f32.bf16.bf16.f32 "
                        "{%0,%1,%2,%3}, {%4,%5,%6,%7}, {%8,%9}, {%0,%1,%2,%3};"
                        : "+f"(d0), "+f"(d1), "+f"(d2), "+f"(d3)
                        : "r"(afr[ks][0]), "r"(afr[ks][1]),
                          "r"(afr[ks][2]), "r"(afr[ks][3]),
                          "r"(b0), "r"(b1));
                }
                // d0:(gid,2tg) d1:(gid,2tg+1) d2:(gid+8,2tg) d3:(gid+8,2tg+1)
                unsigned B0 = __ballot_sync(0xffffffffu, d0 > thrA);
                unsigned B1 = __ballot_sync(0xffffffffu, d1 > thrA);
                unsigned B2 = __ballot_sync(0xffffffffu, d2 > thrA);
                unsigned B3 = __ballot_sync(0xffffffffu, d3 > thrA);
                if (lane < 16) {
                    int row = lane;
                    unsigned ne, no;
                    if (row < 8) { ne = (B0 >> (row * 4)) & 0xF; no = (B1 >> (row * 4)) & 0xF; }
                    else         { ne = (B2 >> ((row - 8) * 4)) & 0xF; no = (B3 >> ((row - 8) * 4)) & 0xF; }
                    unsigned byte =  (ne & 1u)        | ((no & 1u) << 1)
                                  | ((ne & 2u) << 1)  | ((no & 2u) << 2)
                                  | ((ne & 4u) << 2)  | ((no & 4u) << 3)
                                  | ((ne & 8u) << 3)  | ((no & 8u) << 4);
                    wacc |= byte << ((nb & 3) * 8);
                    if ((nb & 3) == 3) {
                        Bm[(R0 + row) * 4 + (nb >> 2)] = wacc;
                        wacc = 0;
                    }
                }
            }
        }
        __syncwarp();

        // ---- candidate passes: 4 groups of 4 rows --------------------------
        #pragma unroll
        for (int g = 0; g < 4; g++) {
            // lane < 16 owns (rowL = g*4 + lane>>2, word = lane&3)
            uint32_t m = 0;
            int cnt = 0;
            int rowL = g * 4 + (lane >> 2);
            if (lane < 16) {
                m = Bm[(R0 + rowL) * 4 + (lane & 3)];
                cnt = __popc(m);
            }
            int pre = cnt;
            #pragma unroll
            for (int off = 1; off < 16; off <<= 1) {
                int n = __shfl_up_sync(0xffffffffu, pre, off);
                if (lane >= off && lane < 16) pre += n;
            }
            int base = pre - cnt;
            int total = __shfl_sync(0xffffffffu, pre, 15);
            {
                int i = 0;
                while (m) {
                    int c = __ffs(m) - 1;
                    m &= m - 1;
                    Ls[wb + base + i] = (rowL << 16) | ((lane & 3) * 32 + c);
                    i++;
                }
            }
            __syncwarp();

            // exact fp32 recompute: SEQUENTIAL single accumulator over d
            // (must match reference gate decisions on borderline scores)
            for (int cb = 0; cb < total; cb += 32) {
                int ci = cb + lane;
                float w = 0.0f;
                if (ci < total) {
                    int e = Ls[wb + ci];
                    int rl = e >> 16, c = e & 0xFFFF;
                    const float4* qr = (const float4*)&Qs[(R0 + rl) * FP];
                    const float4* kc = (const float4*)&Ks[c * FP];
                    float acc = 0.0f;
                    #pragma unroll
                    for (int d = 0; d < 16; d++) {
                        float4 qv = qr[d], kv = kc[d];
                        acc = fmaf(qv.x, kv.x, acc);
                        acc = fmaf(qv.y, kv.y, acc);
                        acc = fmaf(qv.z, kv.z, acc);
                        acc = fmaf(qv.w, kv.w, acc);
                    }
                    float v = acc * scale;
                    if (v > tau) w = __expf(v) - 1.0f;
                }
                if (ci < total) Wl[wb + ci] = w;
            }
            __syncwarp();

            // scatter: list is row-grouped, so O index is compile-time
            #pragma unroll
            for (int j = 0; j < 4; j++) {
                int startj = (j == 0) ? 0 : __shfl_sync(0xffffffffu, pre, j * 4 - 1);
                int endj   = __shfl_sync(0xffffffffu, pre, j * 4 + 3);
                for (int t = startj; t < endj; t++) {
                    float w = Wl[wb + t];               // broadcast
                    int   c = Ls[wb + t] & 0xFFFF;      // broadcast
                    O[g * 4 + j][0] += w * Vs[c * FP + lane];
                    O[g * 4 + j][1] += w * Vs[c * FP + lane + 32];
                    dl[g * 4 + j] += w;
                }
            }
            __syncwarp();
        }
    }

    // ---- combine sumV partials --------------------------------------------
    __syncthreads();
    SVp[svg * 68 + svd] = sv;
    __syncthreads();
    float sv0 = 0.0f, sv1 = 0.0f;
    #pragma unroll
    for (int gg = 0; gg < 8; gg++) {
        sv0 += SVp[gg * 68 + lane];
        sv1 += SVp[gg * 68 + lane + 32];
    }

    // ---- finalize: rows owned by this warp --------------------------------
    const int b_ = bh >> 2, h = bh & 3;
    const int tbase = b_ * 4096 + qt * 256;
    #pragma unroll
    for (int i = 0; i < 16; i++) {
        float inv = 1.0f / (4096.0f + dl[i]);
        int t = tbase + R0 + i;
        g_A[t * 256 + h * 64 + lane]      = (sv0 + O[i][0]) * inv;
        g_A[t * 256 + h * 64 + lane + 32] = (sv1 + O[i][1]) * inv;
    }
}

// ---------------------------------------------------------------------------
// Output projection: out[t,c] = sum_d g_A[t,d] * o_w[c,d] + o_b[c]
// ---------------------------------------------------------------------------
__global__ __launch_bounds__(256) void oproj_kernel(
    const float* __restrict__ ow, const float* __restrict__ ob,
    float* __restrict__ out)
{
    __shared__ float As[64 * PITCH];
    __shared__ float Ws[64 * PITCH];

    const int tr = blockIdx.x * 64;
    const int tc = blockIdx.y * 64;
    const int tid = threadIdx.x;
    const int tx = tid & 15, ty = tid >> 4;

    float acc[4][4] = {};

    for (int kb_ = 0; kb_ < 256; kb_ += 64) {
        for (int idx = tid; idx < 64 * 64; idx += 256) {
            int r = idx >> 6, d = idx & 63;
            As[r * PITCH + d] = g_A[(tr + r) * 256 + kb_ + d];
            Ws[r * PITCH + d] = ow[(tc + r) * 256 + kb_ + d];
        }
        __syncthreads();
        #pragma unroll 8
        for (int d = 0; d < 64; d++) {
            float a[4], b[4];
            #pragma unroll
            for (int i = 0; i < 4; i++) a[i] = As[(ty * 4 + i) * PITCH + d];
            #pragma unroll
            for (int j = 0; j < 4; j++) b[j] = Ws[(tx + 16 * j) * PITCH + d];
            #pragma unroll
            for (int i = 0; i < 4; i++)
                #pragma unroll
                for (int j = 0; j < 4; j++)
                    acc[i][j] += a[i] * b[j];
        }
        __syncthreads();
    }

    #pragma unroll
    for (int i = 0; i < 4; i++) {
        int t = tr + ty * 4 + i;
        #pragma unroll
        for (int j = 0; j < 4; j++) {
            int c = tc + tx + 16 * j;
            out[t * 256 + c] = acc[i][j] + ob[c];
        }
    }
}

// ---------------------------------------------------------------------------
extern "C" void kernel_launch(void* const* d_in, const int* in_sizes, int n_in,
                              void* d_out, int out_size)
{
    const float* x   = (const float*)d_in[0];
    const float* qw  = (const float*)d_in[1];
    const float* qb  = (const float*)d_in[2];
    const float* kw  = (const float*)d_in[3];
    const float* kb  = (const float*)d_in[4];
    const float* vw  = (const float*)d_in[5];
    const float* vb  = (const float*)d_in[6];
    const float* ow  = (const float*)d_in[7];
    const float* ob  = (const float*)d_in[8];
    const float* tau = (const float*)d_in[9];
    float* out = (float*)d_out;

    // QKV projections
    dim3 gq(128, 4, 3);
    qkv_kernel<<<gq, 256>>>(x, qw, qb, kw, kb, vw, vb);

    // attention: HMMA filter + exact sparse recompute
    static bool attr_set = false;
    if (!attr_set) {
        cudaFuncSetAttribute(attn_kernel,
                             cudaFuncAttributeMaxDynamicSharedMemorySize,
                             SM_TOTAL);
        attr_set = true;
    }
    dim3 ga(16, 8);
    attn_kernel<<<ga, 512, SM_TOTAL>>>(tau);

    // output projection
    dim3 go(128, 4);
    oproj_kernel<<<go, 256>>>(ow, ob, out);
}

// round 8
// speedup vs baseline: 1.7755x; 1.0106x over previous
#include <cuda_runtime.h>
#include <cuda_bf16.h>
#include <cstdint>

// SoftThresholdAttention: B=2, N=4096, C=256, H=4, Dh=64
// d_in: 0=x, 1=q_w, 2=q_b, 3=k_w, 4=k_b, 5=v_w, 6=v_b, 7=o_w, 8=o_b, 9=tau

#define PITCH 65   // [c][d] weight tile pitch
#define QP    66   // transposed activation tile pitch (even: 8B row pairs)
#define FP    68   // attn fp32 pitch (16B-aligned rows)
#define HPW   36   // bf16 K tile pitch in u32 words (72 halves = 144B rows)

// Scratch (device globals; no allocation allowed)
__device__ float g_Q[8 * 4096 * 64];   // [b*H+h][n][d]
__device__ float g_K[8 * 4096 * 64];
__device__ float g_V[8 * 4096 * 64];
__device__ float g_A[8192 * 256];      // attention output, [t][c]

// ---- attn smem layout (bytes) ----------------------------------------------
#define SM_QS   0u         // 256 x FP f32   (69632)
#define SM_KS   69632u     // 128 x FP f32   (34816)
#define SM_VS   104448u    // 128 x FP f32   (34816)
#define SM_KH   139264u    // 128 x HPW u32  (18432)  bf16 K tile
#define SM_BM   157696u    // 256 rows x 4 u32 (4096)
#define SM_LS   161792u    // 16 warps x 384 int (24576)
#define SM_WL   186368u    // 16 warps x 384 f32 (24576)
#define SM_SVP  210944u    // 8 x 68 f32 (2176)
#define SM_TOTAL 213120u

// ---- packed fp32x2 helpers (Blackwell FFMA2) -------------------------------
__device__ __forceinline__ unsigned long long pack2(float lo, float hi) {
    unsigned long long r;
    asm("mov.b64 %0, {%1, %2};" : "=l"(r) : "f"(lo), "f"(hi));
    return r;
}
__device__ __forceinline__ void fma2acc(unsigned long long& d,
                                        unsigned long long a,
                                        unsigned long long b) {
    asm("fma.rn.f32x2 %0, %1, %2, %0;" : "+l"(d) : "l"(a), "l"(b));
}
__device__ __forceinline__ float2 unpack2(unsigned long long v) {
    float lo, hi;
    asm("mov.b64 {%0, %1}, %2;" : "=f"(lo), "=f"(hi) : "l"(v));
    return make_float2(lo, hi);
}
// pack two fp32 -> bf16x2 register (lo = first element, as mma expects)
__device__ __forceinline__ uint32_t bf2(float lo, float hi) {
    uint32_t r;
    asm("cvt.rn.bf16x2.f32 %0, %1, %2;" : "=r"(r) : "f"(hi), "f"(lo));
    return r;
}

// ---------------------------------------------------------------------------
// QKV projection via FFMA2: out[t,c] = sum_d x[t,d]*W[c,d] + b[c].
// 64x64 tiles, 256 thr = 8 warps; warp owns 8 rows (4 pairs), cols lane+32jc.
// x tile stored transposed (AsT[d][r]) so row pairs load as one LDS.64.
// ---------------------------------------------------------------------------
__global__ __launch_bounds__(256) void qkv_kernel(
    const float* __restrict__ x,
    const float* __restrict__ qw, const float* __restrict__ qb,
    const float* __restrict__ kw, const float* __restrict__ kb,
    const float* __restrict__ vw, const float* __restrict__ vb)
{
    __shared__ float AsT[64 * QP];     // [d][r]
    __shared__ float Ws[64 * PITCH];   // [c][d]

    const int z = blockIdx.z;
    const float* __restrict__ W    = (z == 0) ? qw : (z == 1) ? kw : vw;
    const float* __restrict__ bias = (z == 0) ? qb : (z == 1) ? kb : vb;
    float* __restrict__ dst        = (z == 0) ? g_Q : (z == 1) ? g_K : g_V;

    const int tr = blockIdx.x * 64;
    const int tc = blockIdx.y * 64;
    const int tid  = threadIdx.x;
    const int warp = tid >> 5;
    const int lane = tid & 31;

    unsigned long long acc2[4][2];
    #pragma unroll
    for (int p = 0; p < 4; p++) { acc2[p][0] = 0ull; acc2[p][1] = 0ull; }

    for (int kb_ = 0; kb_ < 256; kb_ += 64) {
        const float4* X4 = (const float4*)(x + tr * 256 + kb_);
        const float4* W4 = (const float4*)(W + tc * 256 + kb_);
        #pragma unroll
        for (int it = 0; it < 4; it++) {
            int idx = tid + it * 256;      // < 1024
            int r = idx >> 4, d4 = idx & 15;
            float4 v = X4[r * 64 + d4];
            AsT[(d4 * 4 + 0) * QP + r] = v.x;
            AsT[(d4 * 4 + 1) * QP + r] = v.y;
            AsT[(d4 * 4 + 2) * QP + r] = v.z;
            AsT[(d4 * 4 + 3) * QP + r] = v.w;
            float4 wv = W4[r * 64 + d4];
            float* p = &Ws[r * PITCH + d4 * 4];
            p[0] = wv.x; p[1] = wv.y; p[2] = wv.z; p[3] = wv.w;
        }
        __syncthreads();

        #pragma unroll 8
        for (int d = 0; d < 64; d++) {
            const float* arow = &AsT[d * QP + warp * 8];
            unsigned long long ra[4];
            #pragma unroll
            for (int p = 0; p < 4; p++)
                ra[p] = *(const unsigned long long*)(arow + 2 * p);
            unsigned long long bb[2];
            #pragma unroll
            for (int jc = 0; jc < 2; jc++) {
                float b = Ws[(lane + 32 * jc) * PITCH + d];
                bb[jc] = pack2(b, b);
            }
            #pragma unroll
            for (int p = 0; p < 4; p++) {
                fma2acc(acc2[p][0], ra[p], bb[0]);
                fma2acc(acc2[p][1], ra[p], bb[1]);
            }
        }
        __syncthreads();
    }

    #pragma unroll
    for (int p = 0; p < 4; p++) {
        #pragma unroll
        for (int jc = 0; jc < 2; jc++) {
            float2 v = unpack2(acc2[p][jc]);
            int c = tc + lane + 32 * jc;
            int h = c >> 6, dd = c & 63;
            float bv = bias[c];
            int t0 = tr + warp * 8 + 2 * p;
            int b0 = t0 >> 12, n0 = t0 & 4095;
            dst[((b0 * 4 + h) * 4096 + n0) * 64 + dd] = v.x + bv;
            int t1 = t0 + 1;
            int b1 = t1 >> 12, n1 = t1 & 4095;
            dst[((b1 * 4 + h) * 4096 + n1) * 64 + dd] = v.y + bv;
        }
    }
}

// ---------------------------------------------------------------------------
// Attention: bf16 mma.sync filter + exact fp32 recompute of candidates.
// grid (16 q-tiles of 256 rows, 8 bh), block 512 = 16 warps; warp owns 16
// rows, O in registers. Exact dot uses single sequential accumulator over d.
// Candidate passes: 2 groups of 8 rows (all 32 lanes own a (row,word)).
// denom = 4096 + sum(e^v - 1 over v>tau); O = (sumV + sum w*V) / denom.
// ---------------------------------------------------------------------------
__global__ __launch_bounds__(512, 1) void attn_kernel(const float* __restrict__ tau_p)
{
    extern __shared__ char smem[];
    float*    Qs   = (float*)(smem + SM_QS);
    float*    Ks   = (float*)(smem + SM_KS);
    float*    Vs   = (float*)(smem + SM_VS);
    uint32_t* Kh32 = (uint32_t*)(smem + SM_KH);
    uint32_t* Bm   = (uint32_t*)(smem + SM_BM);
    int*      Ls   = (int*)(smem + SM_LS);
    float*    Wl   = (float*)(smem + SM_WL);
    float*    SVp  = (float*)(smem + SM_SVP);

    const int qt = blockIdx.x, bh = blockIdx.y;
    const int tid  = threadIdx.x;
    const int warp = tid >> 5;
    const int lane = tid & 31;
    const int gid  = lane >> 2;      // mma group id (0..7)
    const int tg   = lane & 3;       // thread in group
    const int R0   = warp * 16;      // warp-owned rows [R0, R0+16)
    const float tau   = tau_p[0];
    const float scale = 0.0625f;                 // 256^-0.5
    const float thrA  = (tau - 0.03f) * 16.0f;   // raw-S filter threshold

    const float* __restrict__ Qg = g_Q + (bh * 4096 + qt * 256) * 64;
    const float* __restrict__ Kg = g_K + bh * 4096 * 64;
    const float* __restrict__ Vg = g_V + bh * 4096 * 64;

    // load Q tile (256 x 64) fp32
    {
        const float4* Q4 = (const float4*)Qg;
        #pragma unroll
        for (int it = 0; it < 8; it++) {
            int idx = tid + it * 512;      // < 4096
            int r = idx >> 4, d = (idx & 15) * 4;
            *(float4*)&Qs[r * FP + d] = Q4[idx];
        }
    }
    __syncthreads();

    // A fragments (warp's 16 rows) converted fp32->bf16 from Qs.
    uint32_t afr[4][4];
    #pragma unroll
    for (int ks = 0; ks < 4; ks++) {
        int c0 = ks * 16 + 2 * tg;
        float2 q00 = *(const float2*)&Qs[(R0 + gid) * FP + c0];
        float2 q10 = *(const float2*)&Qs[(R0 + gid + 8) * FP + c0];
        float2 q01 = *(const float2*)&Qs[(R0 + gid) * FP + c0 + 8];
        float2 q11 = *(const float2*)&Qs[(R0 + gid + 8) * FP + c0 + 8];
        afr[ks][0] = bf2(q00.x, q00.y);
        afr[ks][1] = bf2(q10.x, q10.y);
        afr[ks][2] = bf2(q01.x, q01.y);
        afr[ks][3] = bf2(q11.x, q11.y);
    }

    float O[16][2] = {};
    float dl[16]   = {};
    float sv = 0.0f;
    const int svg = tid >> 6, svd = tid & 63;   // 8 groups x 16 keys
    const int wb = warp * 384;

    for (int kt = 0; kt < 32; kt++) {
        __syncthreads();   // prior tile readers done

        // ---- load K/V tiles (128 x 64) fp32 + build bf16 K tile ------------
        {
            const float4* K4 = (const float4*)(Kg + kt * 128 * 64);
            const float4* V4 = (const float4*)(Vg + kt * 128 * 64);
            #pragma unroll
            for (int it = 0; it < 4; it++) {
                int idx = tid + it * 512;      // < 2048
                int r = idx >> 4, d = (idx & 15) * 4;
                float4 kv = K4[idx];
                *(float4*)&Ks[r * FP + d] = kv;
                *(float4*)&Vs[r * FP + d] = V4[idx];
                uint32_t w0 = bf2(kv.x, kv.y);
                uint32_t w1 = bf2(kv.z, kv.w);
                *(uint2*)&Kh32[r * HPW + (d >> 1)] = make_uint2(w0, w1);
            }
        }
        __syncthreads();

        // ---- sumV partial ---------------------------------------------------
        #pragma unroll 8
        for (int k = 0; k < 16; k++)
            sv += Vs[(svg * 16 + k) * FP + svd];

        // ---- approx scores via mma.sync; bitmap for warp's 16 rows ---------
        {
            uint32_t wacc = 0;
            #pragma unroll
            for (int nb = 0; nb < 16; nb++) {
                float d0 = 0.0f, d1 = 0.0f, d2 = 0.0f, d3 = 0.0f;
                #pragma unroll
                for (int ks = 0; ks < 4; ks++) {
                    int kr = nb * 8 + gid;            // key (B col n)
                    uint32_t b0 = Kh32[kr * HPW + ks * 8 + tg];
                    uint32_t b1 = Kh32[kr * HPW + ks * 8 + tg + 4];
                    asm volatile(
                        "mma.sync.aligned.m16n8k16.row.col.f32.bf16.bf16.f32 "
                        "{%0,%1,%2,%3}, {%4,%5,%6,%7}, {%8,%9}, {%0,%1,%2,%3};"
                        : "+f"(d0), "+f"(d1), "+f"(d2), "+f"(d3)
                        : "r"(afr[ks][0]), "r"(afr[ks][1]),
                          "r"(afr[ks][2]), "r"(afr[ks][3]),
                          "r"(b0), "r"(b1));
                }
                // d0:(gid,2tg) d1:(gid,2tg+1) d2:(gid+8,2tg) d3:(gid+8,2tg+1)
                unsigned B0 = __ballot_sync(0xffffffffu, d0 > thrA);
                unsigned B1 = __ballot_sync(0xffffffffu, d1 > thrA);
                unsigned B2 = __ballot_sync(0xffffffffu, d2 > thrA);
                unsigned B3 = __ballot_sync(0xffffffffu, d3 > thrA);
                if (lane < 16) {
                    int row = lane;
                    unsigned ne, no;
                    if (row < 8) { ne = (B0 >> (row * 4)) & 0xF; no = (B1 >> (row * 4)) & 0xF; }
                    else         { ne = (B2 >> ((row - 8) * 4)) & 0xF; no = (B3 >> ((row - 8) * 4)) & 0xF; }
                    unsigned byte =  (ne & 1u)        | ((no & 1u) << 1)
                                  | ((ne & 2u) << 1)  | ((no & 2u) << 2)
                                  | ((ne & 4u) << 2)  | ((no & 4u) << 3)
                                  | ((ne & 8u) << 3)  | ((no & 8u) << 4);
                    wacc |= byte << ((nb & 3) * 8);
                    if ((nb & 3) == 3) {
                        Bm[(R0 + row) * 4 + (nb >> 2)] = wacc;
                        wacc = 0;
                    }
                }
            }
        }
        __syncwarp();

        // ---- candidate passes: 2 groups of 8 rows (all lanes own a word) ---
        #pragma unroll
        for (int g = 0; g < 2; g++) {
            int rowL = g * 8 + (lane >> 2);
            uint32_t m = Bm[(R0 + rowL) * 4 + (lane & 3)];
            int cnt = __popc(m);
            int pre = cnt;
            #pragma unroll
            for (int off = 1; off < 32; off <<= 1) {
                int n = __shfl_up_sync(0xffffffffu, pre, off);
                if (lane >= off) pre += n;
            }
            int base = pre - cnt;
            int total = __shfl_sync(0xffffffffu, pre, 31);
            {
                int i = 0;
                while (m) {
                    int c = __ffs(m) - 1;
                    m &= m - 1;
                    Ls[wb + base + i] = (rowL << 16) | ((lane & 3) * 32 + c);
                    i++;
                }
            }
            __syncwarp();

            // exact fp32 recompute: SEQUENTIAL single accumulator per
            // candidate (matches gate decisions); ILP-2 across two batches.
            for (int cb = 0; cb < total; cb += 64) {
                int ci0 = cb + lane, ci1 = cb + 32 + lane;
                bool v0ok = ci0 < total, v1ok = ci1 < total;
                int e0 = v0ok ? Ls[wb + ci0] : 0;
                int e1 = v1ok ? Ls[wb + ci1] : 0;
                const float4* qr0 = (const float4*)&Qs[(R0 + (e0 >> 16)) * FP];
                const float4* kc0 = (const float4*)&Ks[(e0 & 0xFFFF) * FP];
                const float4* qr1 = (const float4*)&Qs[(R0 + (e1 >> 16)) * FP];
                const float4* kc1 = (const float4*)&Ks[(e1 & 0xFFFF) * FP];
                float acc0 = 0.0f, acc1 = 0.0f;
                #pragma unroll
                for (int d = 0; d < 16; d++) {
                    float4 q0 = qr0[d], k0 = kc0[d];
                    float4 q1 = qr1[d], k1 = kc1[d];
                    acc0 = fmaf(q0.x, k0.x, acc0);
                    acc1 = fmaf(q1.x, k1.x, acc1);
                    acc0 = fmaf(q0.y, k0.y, acc0);
                    acc1 = fmaf(q1.y, k1.y, acc1);
                    acc0 = fmaf(q0.z, k0.z, acc0);
                    acc1 = fmaf(q1.z, k1.z, acc1);
                    acc0 = fmaf(q0.w, k0.w, acc0);
                    acc1 = fmaf(q1.w, k1.w, acc1);
                }
                if (v0ok) {
                    float v = acc0 * scale;
                    Wl[wb + ci0] = (v > tau) ? (__expf(v) - 1.0f) : 0.0f;
                }
                if (v1ok) {
                    float v = acc1 * scale;
                    Wl[wb + ci1] = (v > tau) ? (__expf(v) - 1.0f) : 0.0f;
                }
            }
            __syncwarp();

            // scatter: list is row-grouped, so O index is compile-time
            #pragma unroll
            for (int j = 0; j < 8; j++) {
                int startj = (j == 0) ? 0 : __shfl_sync(0xffffffffu, pre, j * 4 - 1);
                int endj   = __shfl_sync(0xffffffffu, pre, j * 4 + 3);
                for (int t = startj; t < endj; t++) {
                    float w = Wl[wb + t];               // broadcast
                    int   c = Ls[wb + t] & 0xFFFF;      // broadcast
                    O[g * 8 + j][0] += w * Vs[c * FP + lane];
                    O[g * 8 + j][1] += w * Vs[c * FP + lane + 32];
                    dl[g * 8 + j] += w;
                }
            }
            __syncwarp();
        }
    }

    // ---- combine sumV partials --------------------------------------------
    __syncthreads();
    SVp[svg * 68 + svd] = sv;
    __syncthreads();
    float sv0 = 0.0f, sv1 = 0.0f;
    #pragma unroll
    for (int gg = 0; gg < 8; gg++) {
        sv0 += SVp[gg * 68 + lane];
        sv1 += SVp[gg * 68 + lane + 32];
    }

    // ---- finalize: rows owned by this warp --------------------------------
    const int b_ = bh >> 2, h = bh & 3;
    const int tbase = b_ * 4096 + qt * 256;
    #pragma unroll
    for (int i = 0; i < 16; i++) {
        float inv = 1.0f / (4096.0f + dl[i]);
        int t = tbase + R0 + i;
        g_A[t * 256 + h * 64 + lane]      = (sv0 + O[i][0]) * inv;
        g_A[t * 256 + h * 64 + lane + 32] = (sv1 + O[i][1]) * inv;
    }
}

// ---------------------------------------------------------------------------
// Output projection via FFMA2: out[t,c] = sum_d g_A[t,d]*o_w[c,d] + o_b[c]
// ---------------------------------------------------------------------------
__global__ __launch_bounds__(256) void oproj_kernel(
    const float* __restrict__ ow, const float* __restrict__ ob,
    float* __restrict__ out)
{
    __shared__ float AsT[64 * QP];     // [d][r]
    __shared__ float Ws[64 * PITCH];   // [c][d]

    const int tr = blockIdx.x * 64;
    const int tc = blockIdx.y * 64;
    const int tid  = threadIdx.x;
    const int warp = tid >> 5;
    const int lane = tid & 31;

    unsigned long long acc2[4][2];
    #pragma unroll
    for (int p = 0; p < 4; p++) { acc2[p][0] = 0ull; acc2[p][1] = 0ull; }

    for (int kb_ = 0; kb_ < 256; kb_ += 64) {
        const float4* X4 = (const float4*)(g_A + tr * 256 + kb_);
        const float4* W4 = (const float4*)(ow + tc * 256 + kb_);
        #pragma unroll
        for (int it = 0; it < 4; it++) {
            int idx = tid + it * 256;      // < 1024
            int r = idx >> 4, d4 = idx & 15;
            float4 v = X4[r * 64 + d4];
            AsT[(d4 * 4 + 0) * QP + r] = v.x;
            AsT[(d4 * 4 + 1) * QP + r] = v.y;
            AsT[(d4 * 4 + 2) * QP + r] = v.z;
            AsT[(d4 * 4 + 3) * QP + r] = v.w;
            float4 wv = W4[r * 64 + d4];
            float* p = &Ws[r * PITCH + d4 * 4];
            p[0] = wv.x; p[1] = wv.y; p[2] = wv.z; p[3] = wv.w;
        }
        __syncthreads();

        #pragma unroll 8
        for (int d = 0; d < 64; d++) {
            const float* arow = &AsT[d * QP + warp * 8];
            unsigned long long ra[4];
            #pragma unroll
            for (int p = 0; p < 4; p++)
                ra[p] = *(const unsigned long long*)(arow + 2 * p);
            unsigned long long bb[2];
            #pragma unroll
            for (int jc = 0; jc < 2; jc++) {
                float b = Ws[(lane + 32 * jc) * PITCH + d];
                bb[jc] = pack2(b, b);
            }
            #pragma unroll
            for (int p = 0; p < 4; p++) {
                fma2acc(acc2[p][0], ra[p], bb[0]);
                fma2acc(acc2[p][1], ra[p], bb[1]);
            }
        }
        __syncthreads();
    }

    #pragma unroll
    for (int p = 0; p < 4; p++) {
        #pragma unroll
        for (int jc = 0; jc < 2; jc++) {
            float2 v = unpack2(acc2[p][jc]);
            int c = tc + lane + 32 * jc;
            float bv = ob[c];
            int t0 = tr + warp * 8 + 2 * p;
            out[t0 * 256 + c]       = v.x + bv;
            out[(t0 + 1) * 256 + c] = v.y + bv;
        }
    }
}

// ---------------------------------------------------------------------------
extern "C" void kernel_launch(void* const* d_in, const int* in_sizes, int n_in,
                              void* d_out, int out_size)
{
    const float* x   = (const float*)d_in[0];
    const float* qw  = (const float*)d_in[1];
    const float* qb  = (const float*)d_in[2];
    const float* kw  = (const float*)d_in[3];
    const float* kb  = (const float*)d_in[4];
    const float* vw  = (const float*)d_in[5];
    const float* vb  = (const float*)d_in[6];
    const float* ow  = (const float*)d_in[7];
    const float* ob  = (const float*)d_in[8];
    const float* tau = (const float*)d_in[9];
    float* out = (float*)d_out;

    // QKV projections (FFMA2)
    dim3 gq(128, 4, 3);
    qkv_kernel<<<gq, 256>>>(x, qw, qb, kw, kb, vw, vb);

    // attention: HMMA filter + exact sparse recompute
    static bool attr_set = false;
    if (!attr_set) {
        cudaFuncSetAttribute(attn_kernel,
                             cudaFuncAttributeMaxDynamicSharedMemorySize,
                             SM_TOTAL);
        attr_set = true;
    }
    dim3 ga(16, 8);
    attn_kernel<<<ga, 512, SM_TOTAL>>>(tau);

    // output projection (FFMA2)
    dim3 go(128, 4);
    oproj_kernel<<<go, 256>>>(ow, ob, out);
}